// round 3
// baseline (speedup 1.0000x reference)
#include <cuda_runtime.h>
#include <math.h>

#define NB_MAX 32768
#define NW 5
#define NL 20
#define WE_ 50
#define OC_ 30
#define CE_ 32
#define KK_ 3
#define HID_ 100
#define TAGS_ 36
#define KPOOL 160      // padded pooled-feature K (150 real + 10 zero pad)
#define WCAP 100       // word-id projection table capacity (fallback beyond)
#define NPOS 18        // L - K + 1

#define TM 128
#define KC 16
#define AS 136         // padded A-tile stride (floats)

// ---------------- device scratch (static, allocation-free) ----------------
__device__ __align__(16) float g_T[3 * 100 * 32];          // conv lookup: [k][char][oc pad 32]
__device__ __align__(16) float g_WP[NW * WCAP * 128];      // word proj:  [w][wid][j pad 128]
__device__ __align__(16) float g_Wp[KPOOL * HID_];         // repacked fc1 pooled weights [k][j]
__device__ __align__(16) float g_pool[NB_MAX * KPOOL];     // pooled feats; pad cols stay 0 (bss)
__device__ __align__(16) float g_hpart[NB_MAX * 128];      // fc1_b + word-emb contribution
__device__ __align__(16) float g_h[NB_MAX * HID_];         // tanh hidden

// ---------------- K0: build T, WP, repacked Wp ----------------
__global__ void k_init(const float* __restrict__ emb, const float* __restrict__ cemb,
                       const float* __restrict__ convw, const float* __restrict__ fc1w) {
    int stride = gridDim.x * blockDim.x;
    int t0 = blockIdx.x * blockDim.x + threadIdx.x;

    // T[k][c][oc] = sum_ce conv_w[oc][ce][k] * char_emb[c][ce]; pad oc 30..31 with 0
    for (int idx = t0; idx < 3 * 100 * 32; idx += stride) {
        int oc = idx & 31; int rest = idx >> 5; int c = rest % 100; int k = rest / 100;
        float s = 0.f;
        if (oc < OC_) {
            #pragma unroll 8
            for (int ce = 0; ce < CE_; ce++)
                s += convw[(oc * CE_ + ce) * KK_ + k] * cemb[c * CE_ + ce];
        }
        g_T[idx] = s;
    }
    // WP[w][c][j] = emb[c] . fc1_w[j, w*80 : w*80+50]
    for (int idx = t0; idx < NW * WCAP * HID_; idx += stride) {
        int j = idx % HID_; int rest = idx / HID_; int c = rest % WCAP; int w = rest / WCAP;
        float s = 0.f;
        #pragma unroll 10
        for (int d = 0; d < WE_; d++)
            s += emb[c * WE_ + d] * fc1w[j * 400 + w * 80 + d];
        g_WP[((w * WCAP + c) << 7) + j] = s;
    }
    // Wp[k][j]: pooled part of fc1_w, k = w*30+oc, zero-pad k>=150
    for (int idx = t0; idx < KPOOL * HID_; idx += stride) {
        int j = idx % HID_; int kk = idx / HID_;
        float v = 0.f;
        if (kk < NW * OC_) {
            int w = kk / OC_, oc = kk % OC_;
            v = fc1w[j * 400 + w * 80 + WE_ + oc];
        }
        g_Wp[kk * HID_ + j] = v;
    }
}

// ---------------- K1: conv-as-table + maxpool; 4 words per warp ----------------
__global__ __launch_bounds__(128) void k_pool(const int* __restrict__ inp,
                                              const float* __restrict__ convb, int nTasks) {
    __shared__ int sch[16 * 21];   // 16 (sample,word) tasks * 21 ints each
    int tid = threadIdx.x;
    int base = blockIdx.x * 16;
    int lim = nTasks * 21 - base * 21;       // remaining ints
    for (int idx = tid; idx < 16 * 21; idx += 128)
        sch[idx] = (idx < lim) ? inp[base * 21 + idx] : 0;
    __syncthreads();

    int taskL = tid >> 3;          // 0..15
    int oc4 = tid & 7;             // float4 lane within oc dim
    int task = base + taskL;
    if (task >= nTasks) return;

    const float4* T4 = reinterpret_cast<const float4*>(g_T);
    const int* ch = sch + taskL * 21 + 1;    // chars
    float ax = -INFINITY, ay = -INFINITY, az = -INFINITY, aw = -INFINITY;
    #pragma unroll
    for (int p = 0; p < NPOS; p++) {
        int c0 = ch[p], c1 = ch[p + 1], c2 = ch[p + 2];
        float4 t0 = T4[(0 * 100 + c0) * 8 + oc4];
        float4 t1 = T4[(1 * 100 + c1) * 8 + oc4];
        float4 t2 = T4[(2 * 100 + c2) * 8 + oc4];
        ax = fmaxf(ax, t0.x + t1.x + t2.x);
        ay = fmaxf(ay, t0.y + t1.y + t2.y);
        az = fmaxf(az, t0.z + t1.z + t2.z);
        aw = fmaxf(aw, t0.w + t1.w + t2.w);
    }
    int s = task / NW, w = task % NW;
    int oc = oc4 * 4;
    float* dst = g_pool + s * KPOOL + w * OC_ + oc;
    if (oc + 0 < OC_) dst[0] = ax + convb[oc + 0];
    if (oc + 1 < OC_) dst[1] = ay + convb[oc + 1];
    if (oc + 2 < OC_) dst[2] = az + convb[oc + 2];
    if (oc + 3 < OC_) dst[3] = aw + convb[oc + 3];
}

// ---------------- K2: hpart[s][j] = fc1_b[j] + sum_w word-emb contribution ----------------
__global__ __launch_bounds__(256) void k_hpart(const int* __restrict__ inp,
        const float* __restrict__ fc1b, const float* __restrict__ emb,
        const float* __restrict__ fc1w, int nB) {
    int s = (blockIdx.x * blockDim.x + threadIdx.x) >> 5;
    int lane = threadIdx.x & 31;
    if (s >= nB) return;
    int wid = (lane < NW) ? inp[s * 105 + lane * 21] : 0;
    int ws[5];
    ws[0] = __shfl_sync(0xffffffffu, wid, 0);
    ws[1] = __shfl_sync(0xffffffffu, wid, 1);
    ws[2] = __shfl_sync(0xffffffffu, wid, 2);
    ws[3] = __shfl_sync(0xffffffffu, wid, 3);
    ws[4] = __shfl_sync(0xffffffffu, wid, 4);
    #pragma unroll
    for (int jj = 0; jj < 4; jj++) {
        int j = jj * 32 + lane;
        bool act = (j < HID_);
        float acc = act ? fc1b[j] : 0.f;
        #pragma unroll
        for (int w = 0; w < NW; w++) {
            int c = ws[w];                      // uniform across warp
            if (c < WCAP) {
                if (act) acc += g_WP[((w * WCAP + c) << 7) + j];
            } else if (act) {
                // fallback: honest projection (correct for any vocab id)
                for (int d = 0; d < WE_; d++)
                    acc += emb[c * WE_ + d] * fc1w[j * 400 + w * 80 + d];
            }
        }
        if (act) g_hpart[s * 128 + j] = acc;
    }
}

// ---------------- K3: h = tanh(pool . Wp + hpart); M-tiled fp32 GEMM ----------------
__global__ __launch_bounds__(320, 2) void k_fc1(int nB) {
    extern __shared__ float sm[];
    float* Wps = sm;                       // [KPOOL][HID_] = 16000 floats
    float* As  = sm + KPOOL * HID_;        // [2][KC][AS]   = 4352 floats
    int tid = threadIdx.x;
    int m0 = blockIdx.x * TM;

    for (int idx = tid; idx < KPOOL * HID_; idx += 320) Wps[idx] = g_Wp[idx];
    for (int idx = tid; idx < KC * TM; idx += 320) {
        int m = idx >> 4, kk = idx & 15;
        int row = m0 + m;
        As[kk * AS + m] = (row < nB) ? g_pool[row * KPOOL + kk] : 0.f;
    }
    __syncthreads();

    int tx = tid & 15;      // 16 m-groups of 8 rows
    int ty = tid >> 4;      // 20 n-groups of 5 cols
    float acc[8][5];
    #pragma unroll
    for (int i = 0; i < 8; i++)
        #pragma unroll
        for (int u = 0; u < 5; u++) acc[i][u] = 0.f;

    const int NCH = KPOOL / KC;   // 10
    for (int ck = 0; ck < NCH; ck++) {
        int buf = ck & 1;
        if (ck + 1 < NCH) {       // prefetch next chunk into other buffer
            int k0 = (ck + 1) * KC;
            int nb = buf ^ 1;
            for (int idx = tid; idx < KC * TM; idx += 320) {
                int m = idx >> 4, kk = idx & 15;
                int row = m0 + m;
                As[(nb * KC + kk) * AS + m] = (row < nB) ? g_pool[row * KPOOL + k0 + kk] : 0.f;
            }
        }
        const float* Ab = As + buf * KC * AS;
        const float* Wb = Wps + ck * KC * HID_ + ty * 5;
        #pragma unroll
        for (int kk = 0; kk < KC; kk++) {
            const float4* ap = reinterpret_cast<const float4*>(Ab + kk * AS + tx * 8);
            float4 a0 = ap[0], a1 = ap[1];
            float wv[5];
            #pragma unroll
            for (int u = 0; u < 5; u++) wv[u] = Wb[kk * HID_ + u];
            float a[8] = {a0.x, a0.y, a0.z, a0.w, a1.x, a1.y, a1.z, a1.w};
            #pragma unroll
            for (int i = 0; i < 8; i++)
                #pragma unroll
                for (int u = 0; u < 5; u++)
                    acc[i][u] = fmaf(a[i], wv[u], acc[i][u]);
        }
        __syncthreads();
    }

    #pragma unroll
    for (int i = 0; i < 8; i++) {
        int m = m0 + tx * 8 + i;
        if (m < nB) {
            #pragma unroll
            for (int u = 0; u < 5; u++) {
                int n = ty * 5 + u;
                float v = acc[i][u] + g_hpart[m * 128 + n];
                g_h[m * HID_ + n] = tanhf(v);
            }
        }
    }
}

// ---------------- K4: out = h @ out_w^T + out_b ----------------
__global__ __launch_bounds__(256) void k_out(const float* __restrict__ outw,
        const float* __restrict__ outb, float* __restrict__ out, int nB) {
    extern __shared__ float sm[];
    float* Hs = sm;               // [128][101]
    float* Ws = sm + 128 * 101;   // [36*100]
    int tid = threadIdx.x;
    int m0 = blockIdx.x * 128;
    for (int idx = tid; idx < 128 * HID_; idx += 256) {
        int m = idx / HID_, k = idx - m * HID_;
        int row = m0 + m;
        Hs[m * 101 + k] = (row < nB) ? g_h[row * HID_ + k] : 0.f;
    }
    for (int idx = tid; idx < TAGS_ * HID_; idx += 256) Ws[idx] = outw[idx];
    __syncthreads();

    int rg = tid & 63, tg = tid >> 6;   // 64 row-groups(2 rows) x 4 tag-groups(9 tags)
    int r0 = rg * 2;
    float acc[2][9];
    #pragma unroll
    for (int i = 0; i < 2; i++)
        #pragma unroll
        for (int u = 0; u < 9; u++) acc[i][u] = 0.f;

    const float* h0p = Hs + r0 * 101;
    const float* h1p = Hs + (r0 + 1) * 101;
    const float* wb  = Ws + tg * 9 * HID_;
    #pragma unroll 4
    for (int k = 0; k < HID_; k++) {
        float h0 = h0p[k], h1 = h1p[k];
        #pragma unroll
        for (int u = 0; u < 9; u++) {
            float wv = wb[u * HID_ + k];
            acc[0][u] = fmaf(h0, wv, acc[0][u]);
            acc[1][u] = fmaf(h1, wv, acc[1][u]);
        }
    }
    #pragma unroll
    for (int i = 0; i < 2; i++) {
        int m = m0 + r0 + i;
        if (m < nB) {
            #pragma unroll
            for (int u = 0; u < 9; u++)
                out[m * TAGS_ + tg * 9 + u] = acc[i][u] + outb[tg * 9 + u];
        }
    }
}

// ---------------- launch ----------------
extern "C" void kernel_launch(void* const* d_in, const int* in_sizes, int n_in,
                              void* d_out, int out_size) {
    const int*   inp   = (const int*)  d_in[0];
    const float* emb   = (const float*)d_in[1];
    const float* cemb  = (const float*)d_in[2];
    const float* convw = (const float*)d_in[3];
    const float* convb = (const float*)d_in[4];
    const float* fc1w  = (const float*)d_in[5];
    const float* fc1b  = (const float*)d_in[6];
    const float* outw  = (const float*)d_in[7];
    const float* outb  = (const float*)d_in[8];
    float* out = (float*)d_out;

    int nB = in_sizes[0] / (NW * (1 + NL));
    if (nB > NB_MAX) nB = NB_MAX;

    int fc1_smem = (KPOOL * HID_ + 2 * KC * AS) * (int)sizeof(float);   // 81408 B
    int out_smem = (128 * 101 + TAGS_ * HID_) * (int)sizeof(float);     // 66112 B
    cudaFuncSetAttribute(k_fc1, cudaFuncAttributeMaxDynamicSharedMemorySize, fc1_smem);
    cudaFuncSetAttribute(k_out, cudaFuncAttributeMaxDynamicSharedMemorySize, out_smem);

    k_init<<<128, 256>>>(emb, cemb, convw, fc1w);
    int nTasks = nB * NW;
    k_pool<<<(nTasks + 15) / 16, 128>>>(inp, convb, nTasks);
    k_hpart<<<(nB * 32 + 255) / 256, 256>>>(inp, fc1b, emb, fc1w, nB);
    k_fc1<<<(nB + TM - 1) / TM, 320, fc1_smem>>>(nB);
    k_out<<<(nB + 127) / 128, 256, out_smem>>>(outw, outb, out, nB);
}

// round 4
// speedup vs baseline: 1.1909x; 1.1909x over previous
#include <cuda_runtime.h>
#include <math.h>

#define NB_MAX 32768
#define NW 5
#define NL 20
#define WE_ 50
#define OC_ 30
#define CE_ 32
#define KK_ 3
#define HID_ 100
#define TAGS_ 36
#define KPOOL 160      // padded pooled-feature K (150 real + 10 zero pad)
#define WCAP 100       // word-id projection table capacity (fallback beyond)
#define NPOS 18        // L - K + 1

#define TM 128
#define KC 16
#define AS 132         // padded A-tile stride (floats); 528B = 33*16 -> f4 aligned
#define NCH (KPOOL / KC)   // 10

// ---------------- device scratch (static, allocation-free) ----------------
__device__ __align__(16) float g_T[3 * 100 * 32];          // conv lookup: [k][char][oc pad 32]
__device__ __align__(16) float g_WP[NW * WCAP * 128];      // word proj:  [w][wid][j pad 128]
__device__ __align__(16) float g_Wp[KPOOL * HID_];         // repacked fc1 pooled weights [k][j]
__device__ __align__(16) float g_pool[NB_MAX * KPOOL];     // pooled feats; pad cols stay 0 (bss)
__device__ __align__(16) float g_hpart[NB_MAX * 128];      // fc1_b + word-emb contribution
__device__ __align__(16) float g_h[NB_MAX * HID_];         // tanh hidden

// ---------------- K0: build T, WP, repacked Wp ----------------
__global__ void k_init(const float* __restrict__ emb, const float* __restrict__ cemb,
                       const float* __restrict__ convw, const float* __restrict__ fc1w) {
    int stride = gridDim.x * blockDim.x;
    int t0 = blockIdx.x * blockDim.x + threadIdx.x;

    // T[k][c][oc] = sum_ce conv_w[oc][ce][k] * char_emb[c][ce]; pad oc 30..31 with 0
    for (int idx = t0; idx < 3 * 100 * 32; idx += stride) {
        int oc = idx & 31; int rest = idx >> 5; int c = rest % 100; int k = rest / 100;
        float s = 0.f;
        if (oc < OC_) {
            #pragma unroll 8
            for (int ce = 0; ce < CE_; ce++)
                s += convw[(oc * CE_ + ce) * KK_ + k] * cemb[c * CE_ + ce];
        }
        g_T[idx] = s;
    }
    // WP[w][c][j] = emb[c] . fc1_w[j, w*80 : w*80+50]
    for (int idx = t0; idx < NW * WCAP * HID_; idx += stride) {
        int j = idx % HID_; int rest = idx / HID_; int c = rest % WCAP; int w = rest / WCAP;
        float s = 0.f;
        #pragma unroll 10
        for (int d = 0; d < WE_; d++)
            s += emb[c * WE_ + d] * fc1w[j * 400 + w * 80 + d];
        g_WP[((w * WCAP + c) << 7) + j] = s;
    }
    // Wp[k][j]: pooled part of fc1_w, k = w*30+oc, zero-pad k>=150
    for (int idx = t0; idx < KPOOL * HID_; idx += stride) {
        int j = idx % HID_; int kk = idx / HID_;
        float v = 0.f;
        if (kk < NW * OC_) {
            int w = kk / OC_, oc = kk % OC_;
            v = fc1w[j * 400 + w * 80 + WE_ + oc];
        }
        g_Wp[kk * HID_ + j] = v;
    }
}

// ---------------- K1: conv-as-table + maxpool; 4 words per warp ----------------
__global__ __launch_bounds__(128) void k_pool(const int* __restrict__ inp,
                                              const float* __restrict__ convb, int nTasks) {
    __shared__ int sch[16 * 21];   // 16 (sample,word) tasks * 21 ints each
    int tid = threadIdx.x;
    int base = blockIdx.x * 16;
    int lim = nTasks * 21 - base * 21;       // remaining ints
    for (int idx = tid; idx < 16 * 21; idx += 128)
        sch[idx] = (idx < lim) ? inp[base * 21 + idx] : 0;
    __syncthreads();

    int taskL = tid >> 3;          // 0..15
    int oc4 = tid & 7;             // float4 lane within oc dim
    int task = base + taskL;
    if (task >= nTasks) return;

    const float4* T4 = reinterpret_cast<const float4*>(g_T);
    const int* ch = sch + taskL * 21 + 1;    // chars
    float ax = -INFINITY, ay = -INFINITY, az = -INFINITY, aw = -INFINITY;
    #pragma unroll
    for (int p = 0; p < NPOS; p++) {
        int c0 = ch[p], c1 = ch[p + 1], c2 = ch[p + 2];
        float4 t0 = T4[(0 * 100 + c0) * 8 + oc4];
        float4 t1 = T4[(1 * 100 + c1) * 8 + oc4];
        float4 t2 = T4[(2 * 100 + c2) * 8 + oc4];
        ax = fmaxf(ax, t0.x + t1.x + t2.x);
        ay = fmaxf(ay, t0.y + t1.y + t2.y);
        az = fmaxf(az, t0.z + t1.z + t2.z);
        aw = fmaxf(aw, t0.w + t1.w + t2.w);
    }
    int s = task / NW, w = task % NW;
    int oc = oc4 * 4;
    float* dst = g_pool + s * KPOOL + w * OC_ + oc;
    if (oc + 0 < OC_) dst[0] = ax + convb[oc + 0];
    if (oc + 1 < OC_) dst[1] = ay + convb[oc + 1];
    if (oc + 2 < OC_) dst[2] = az + convb[oc + 2];
    if (oc + 3 < OC_) dst[3] = aw + convb[oc + 3];
}

// ---------------- K2: hpart[s][j] = fc1_b[j] + sum_w word-emb contribution ----------------
__global__ __launch_bounds__(256) void k_hpart(const int* __restrict__ inp,
        const float* __restrict__ fc1b, const float* __restrict__ emb,
        const float* __restrict__ fc1w, int nB) {
    int s = (blockIdx.x * blockDim.x + threadIdx.x) >> 5;
    int lane = threadIdx.x & 31;
    if (s >= nB) return;
    int wid = (lane < NW) ? inp[s * 105 + lane * 21] : 0;
    int ws[5];
    ws[0] = __shfl_sync(0xffffffffu, wid, 0);
    ws[1] = __shfl_sync(0xffffffffu, wid, 1);
    ws[2] = __shfl_sync(0xffffffffu, wid, 2);
    ws[3] = __shfl_sync(0xffffffffu, wid, 3);
    ws[4] = __shfl_sync(0xffffffffu, wid, 4);
    #pragma unroll
    for (int jj = 0; jj < 4; jj++) {
        int j = jj * 32 + lane;
        bool act = (j < HID_);
        float acc = act ? fc1b[j] : 0.f;
        #pragma unroll
        for (int w = 0; w < NW; w++) {
            int c = ws[w];                      // uniform across warp
            if (c < WCAP) {
                if (act) acc += g_WP[((w * WCAP + c) << 7) + j];
            } else if (act) {
                // fallback: honest projection (correct for any vocab id)
                for (int d = 0; d < WE_; d++)
                    acc += emb[c * WE_ + d] * fc1w[j * 400 + w * 80 + d];
            }
        }
        if (act) g_hpart[s * 128 + j] = acc;
    }
}

// ---------------- K3: h = tanh(pool . Wp + hpart) -----------------------------
// 640 threads = 32 m-lanes (x4 rows) * 20 n-warps (x5 cols). 2 CTAs/SM forced.
// Double-buffered A/W chunks (KC=16) with register prefetch; hpart staged
// through shared for fully coalesced global traffic.
__global__ __launch_bounds__(640, 2) void k_fc1(int nB) {
    extern __shared__ float sm[];
    float* Asm = sm;                          // [2][KC][AS] = 4224 floats
    float* Wsm = sm + 2 * KC * AS;            // [2][KC][100] = 3200 floats
    // epilogue overlay: Hp = sm, [128][101] = 12928 floats

    int tid = threadIdx.x;
    int lane = tid & 31;          // m-group: rows lane*4 .. +3
    int wy = tid >> 5;            // n-group: cols wy*5 .. +4
    int m0 = blockIdx.x * TM;

    // loader roles
    int rowL = tid >> 2, kpL = tid & 3;           // A loader (tid < 512)
    bool hasA = (tid < 512);
    int widx = (tid >= 512) ? (tid - 512) : (tid + 128);
    bool hasW = (tid >= 512) || (tid < 272);
    const float4* Wp4 = reinterpret_cast<const float4*>(g_Wp);
    float4* Wc4 = reinterpret_cast<float4*>(Wsm);

    float4 pA = make_float4(0.f, 0.f, 0.f, 0.f);
    float4 pW = make_float4(0.f, 0.f, 0.f, 0.f);

    // prologue: fetch + store chunk 0
    if (hasA) {
        int m = m0 + rowL;
        if (m < nB) pA = *reinterpret_cast<const float4*>(g_pool + m * KPOOL + kpL * 4);
    }
    if (hasW) pW = Wp4[widx];
    if (hasA) {
        int b0 = (kpL * 4) * AS + rowL;
        Asm[b0] = pA.x; Asm[b0 + AS] = pA.y; Asm[b0 + 2 * AS] = pA.z; Asm[b0 + 3 * AS] = pA.w;
    }
    if (hasW) Wc4[widx] = pW;
    __syncthreads();

    float acc[4][5];
    #pragma unroll
    for (int i = 0; i < 4; i++)
        #pragma unroll
        for (int u = 0; u < 5; u++) acc[i][u] = 0.f;

    for (int ck = 0; ck < NCH; ck++) {
        int b = ck & 1;
        if (ck + 1 < NCH) {       // prefetch next chunk into registers
            int k0 = (ck + 1) * KC;
            if (hasA) {
                int m = m0 + rowL;
                pA = (m < nB) ? *reinterpret_cast<const float4*>(g_pool + m * KPOOL + k0 + kpL * 4)
                              : make_float4(0.f, 0.f, 0.f, 0.f);
            }
            if (hasW) pW = Wp4[(ck + 1) * 400 + widx];
        }
        const float* Ab = Asm + b * KC * AS;
        const float* Wb = Wsm + b * KC * HID_ + wy * 5;
        #pragma unroll
        for (int kk = 0; kk < KC; kk++) {
            float4 a = *reinterpret_cast<const float4*>(Ab + kk * AS + (lane << 2));
            float w0 = Wb[kk * HID_ + 0], w1 = Wb[kk * HID_ + 1], w2 = Wb[kk * HID_ + 2];
            float w3 = Wb[kk * HID_ + 3], w4 = Wb[kk * HID_ + 4];
            acc[0][0] = fmaf(a.x, w0, acc[0][0]); acc[0][1] = fmaf(a.x, w1, acc[0][1]);
            acc[0][2] = fmaf(a.x, w2, acc[0][2]); acc[0][3] = fmaf(a.x, w3, acc[0][3]);
            acc[0][4] = fmaf(a.x, w4, acc[0][4]);
            acc[1][0] = fmaf(a.y, w0, acc[1][0]); acc[1][1] = fmaf(a.y, w1, acc[1][1]);
            acc[1][2] = fmaf(a.y, w2, acc[1][2]); acc[1][3] = fmaf(a.y, w3, acc[1][3]);
            acc[1][4] = fmaf(a.y, w4, acc[1][4]);
            acc[2][0] = fmaf(a.z, w0, acc[2][0]); acc[2][1] = fmaf(a.z, w1, acc[2][1]);
            acc[2][2] = fmaf(a.z, w2, acc[2][2]); acc[2][3] = fmaf(a.z, w3, acc[2][3]);
            acc[2][4] = fmaf(a.z, w4, acc[2][4]);
            acc[3][0] = fmaf(a.w, w0, acc[3][0]); acc[3][1] = fmaf(a.w, w1, acc[3][1]);
            acc[3][2] = fmaf(a.w, w2, acc[3][2]); acc[3][3] = fmaf(a.w, w3, acc[3][3]);
            acc[3][4] = fmaf(a.w, w4, acc[3][4]);
        }
        if (ck + 1 < NCH) {       // store prefetched chunk into other buffer
            int nb = b ^ 1;
            if (hasA) {
                int b0 = nb * KC * AS + (kpL * 4) * AS + rowL;
                Asm[b0] = pA.x; Asm[b0 + AS] = pA.y; Asm[b0 + 2 * AS] = pA.z; Asm[b0 + 3 * AS] = pA.w;
            }
            if (hasW) Wc4[nb * 400 + widx] = pW;
        }
        __syncthreads();
    }

    // ---- epilogue: stage hpart coalesced, add + tanh, store h coalesced ----
    float* Hp = sm;   // [128][101]
    for (int idx = tid; idx < 128 * 25; idx += 640) {
        int r = idx / 25, c4 = idx - r * 25;
        int m = m0 + r;
        float4 v = (m < nB) ? *reinterpret_cast<const float4*>(g_hpart + m * 128 + c4 * 4)
                            : make_float4(0.f, 0.f, 0.f, 0.f);
        int b0 = r * 101 + c4 * 4;
        Hp[b0] = v.x; Hp[b0 + 1] = v.y; Hp[b0 + 2] = v.z; Hp[b0 + 3] = v.w;
    }
    __syncthreads();
    #pragma unroll
    for (int i = 0; i < 4; i++) {
        int m = (lane << 2) + i;
        #pragma unroll
        for (int u = 0; u < 5; u++) {
            int col = wy * 5 + u;
            Hp[m * 101 + col] = tanhf(acc[i][u] + Hp[m * 101 + col]);
        }
    }
    __syncthreads();
    for (int idx = tid; idx < 128 * 25; idx += 640) {
        int r = idx / 25, c4 = idx - r * 25;
        int m = m0 + r;
        if (m < nB) {
            int b0 = r * 101 + c4 * 4;
            float4 v = make_float4(Hp[b0], Hp[b0 + 1], Hp[b0 + 2], Hp[b0 + 3]);
            *reinterpret_cast<float4*>(g_h + m * HID_ + c4 * 4) = v;
        }
    }
}

// ---------------- K4: out = h @ out_w^T + out_b ----------------
__global__ __launch_bounds__(256) void k_out(const float* __restrict__ outw,
        const float* __restrict__ outb, float* __restrict__ out, int nB) {
    extern __shared__ float sm[];
    float* Hs = sm;               // [128][101]
    float* Ws = sm + 128 * 101;   // [36*100]
    int tid = threadIdx.x;
    int m0 = blockIdx.x * 128;
    for (int idx = tid; idx < 128 * HID_; idx += 256) {
        int m = idx / HID_, k = idx - m * HID_;
        int row = m0 + m;
        Hs[m * 101 + k] = (row < nB) ? g_h[row * HID_ + k] : 0.f;
    }
    for (int idx = tid; idx < TAGS_ * HID_; idx += 256) Ws[idx] = outw[idx];
    __syncthreads();

    int rg = tid & 63, tg = tid >> 6;   // 64 row-groups(2 rows) x 4 tag-groups(9 tags)
    int r0 = rg * 2;
    float acc[2][9];
    #pragma unroll
    for (int i = 0; i < 2; i++)
        #pragma unroll
        for (int u = 0; u < 9; u++) acc[i][u] = 0.f;

    const float* h0p = Hs + r0 * 101;
    const float* h1p = Hs + (r0 + 1) * 101;
    const float* wb  = Ws + tg * 9 * HID_;
    #pragma unroll 4
    for (int k = 0; k < HID_; k++) {
        float h0 = h0p[k], h1 = h1p[k];
        #pragma unroll
        for (int u = 0; u < 9; u++) {
            float wv = wb[u * HID_ + k];
            acc[0][u] = fmaf(h0, wv, acc[0][u]);
            acc[1][u] = fmaf(h1, wv, acc[1][u]);
        }
    }
    #pragma unroll
    for (int i = 0; i < 2; i++) {
        int m = m0 + r0 + i;
        if (m < nB) {
            #pragma unroll
            for (int u = 0; u < 9; u++)
                out[m * TAGS_ + tg * 9 + u] = acc[i][u] + outb[tg * 9 + u];
        }
    }
}

// ---------------- launch ----------------
extern "C" void kernel_launch(void* const* d_in, const int* in_sizes, int n_in,
                              void* d_out, int out_size) {
    const int*   inp   = (const int*)  d_in[0];
    const float* emb   = (const float*)d_in[1];
    const float* cemb  = (const float*)d_in[2];
    const float* convw = (const float*)d_in[3];
    const float* convb = (const float*)d_in[4];
    const float* fc1w  = (const float*)d_in[5];
    const float* fc1b  = (const float*)d_in[6];
    const float* outw  = (const float*)d_in[7];
    const float* outb  = (const float*)d_in[8];
    float* out = (float*)d_out;

    int nB = in_sizes[0] / (NW * (1 + NL));
    if (nB > NB_MAX) nB = NB_MAX;

    int fc1_smem = 128 * 101 * (int)sizeof(float);                       // 51712 B (union)
    int out_smem = (128 * 101 + TAGS_ * HID_) * (int)sizeof(float);      // 66112 B
    cudaFuncSetAttribute(k_fc1, cudaFuncAttributeMaxDynamicSharedMemorySize, fc1_smem);
    cudaFuncSetAttribute(k_out, cudaFuncAttributeMaxDynamicSharedMemorySize, out_smem);

    k_init<<<128, 256>>>(emb, cemb, convw, fc1w);
    int nTasks = nB * NW;
    k_pool<<<(nTasks + 15) / 16, 128>>>(inp, convb, nTasks);
    k_hpart<<<(nB * 32 + 255) / 256, 256>>>(inp, fc1b, emb, fc1w, nB);
    k_fc1<<<(nB + TM - 1) / TM, 640, fc1_smem>>>(nB);
    k_out<<<(nB + 127) / 128, 256, out_smem>>>(outw, outb, out, nB);
}

// round 7
// speedup vs baseline: 1.2909x; 1.0840x over previous
#include <cuda_runtime.h>
#include <math.h>
#include <stdint.h>

#define NB_MAX 32768
#define NW 5
#define NL 20
#define WE_ 50
#define OC_ 30
#define CE_ 32
#define HID_ 100
#define TAGS_ 36
#define KPOOL 160
#define WCAP 100
#define NPOS 18

#define TM 128
#define KC 16
#define AS 132
#define NCH (KPOOL / KC)   // 10
#define NT 800             // fc1 threads

// f32x2 packed helpers (sm_103a)
#define FMA2(acc, a, b) asm("fma.rn.f32x2 %0, %1, %2, %0;" : "+l"(acc) : "l"(a), "l"(b))
#define PK2(d, lo, hi) asm("mov.b64 %0, {%1, %2};" : "=l"(d) : "r"(__float_as_uint(lo)), "r"(__float_as_uint(hi)))
union F2U { unsigned long long u; float2 f; };

// ---------------- device scratch ----------------
__device__ __align__(16) float g_T[3 * 100 * 32];
__device__ __align__(16) float g_WP[NW * WCAP * 128];
__device__ __align__(16) float g_Wp[KPOOL * HID_];
__device__ __align__(16) float g_pool[NB_MAX * KPOOL];
__device__ __align__(16) float g_hpart[NB_MAX * 128];

// ---------------- K0: build T, WP, Wp ----------------
__global__ void k_init(const float* __restrict__ emb, const float* __restrict__ cemb,
                       const float* __restrict__ convw, const float* __restrict__ fc1w) {
    int stride = gridDim.x * blockDim.x;
    int t0 = blockIdx.x * blockDim.x + threadIdx.x;
    for (int idx = t0; idx < 3 * 100 * 32; idx += stride) {
        int oc = idx & 31; int rest = idx >> 5; int c = rest % 100; int k = rest / 100;
        float s = 0.f;
        if (oc < OC_) {
            #pragma unroll 8
            for (int ce = 0; ce < CE_; ce++)
                s += convw[(oc * CE_ + ce) * 3 + k] * cemb[c * CE_ + ce];
        }
        g_T[idx] = s;
    }
    for (int idx = t0; idx < NW * WCAP * HID_; idx += stride) {
        int j = idx % HID_; int rest = idx / HID_; int c = rest % WCAP; int w = rest / WCAP;
        float s = 0.f;
        #pragma unroll 10
        for (int d = 0; d < WE_; d++)
            s += emb[c * WE_ + d] * fc1w[j * 400 + w * 80 + d];
        g_WP[((w * WCAP + c) << 7) + j] = s;
    }
    for (int idx = t0; idx < KPOOL * HID_; idx += stride) {
        int j = idx % HID_; int kk = idx / HID_;
        float v = 0.f;
        if (kk < NW * OC_) {
            int w = kk / OC_, oc = kk % OC_;
            v = fc1w[j * 400 + w * 80 + WE_ + oc];
        }
        g_Wp[kk * HID_ + j] = v;
    }
}

// ---------------- K1: conv-as-table + maxpool ----------------
__global__ __launch_bounds__(256) void k_pool(const int* __restrict__ inp,
                                              const float* __restrict__ convb, int nTasks) {
    __shared__ int sch[32 * 21];
    int tid = threadIdx.x;
    int base = blockIdx.x * 32;
    int lim = nTasks * 21 - base * 21;
    for (int idx = tid; idx < 32 * 21; idx += 256)
        sch[idx] = (idx < lim) ? inp[base * 21 + idx] : 0;
    __syncthreads();

    int taskL = tid >> 3;
    int oc4 = tid & 7;
    int task = base + taskL;
    if (task >= nTasks) return;

    const float4* T4 = reinterpret_cast<const float4*>(g_T);
    const int* ch = sch + taskL * 21 + 1;
    float ax = -INFINITY, ay = -INFINITY, az = -INFINITY, aw = -INFINITY;
    #pragma unroll
    for (int p = 0; p < NPOS; p++) {
        int c0 = ch[p], c1 = ch[p + 1], c2 = ch[p + 2];
        float4 t0 = T4[(0 * 100 + c0) * 8 + oc4];
        float4 t1 = T4[(1 * 100 + c1) * 8 + oc4];
        float4 t2 = T4[(2 * 100 + c2) * 8 + oc4];
        ax = fmaxf(ax, t0.x + t1.x + t2.x);
        ay = fmaxf(ay, t0.y + t1.y + t2.y);
        az = fmaxf(az, t0.z + t1.z + t2.z);
        aw = fmaxf(aw, t0.w + t1.w + t2.w);
    }
    int s = task / NW, w = task % NW;
    int oc = oc4 * 4;
    float* dst = g_pool + s * KPOOL + w * OC_ + oc;
    if (oc + 0 < OC_) dst[0] = ax + convb[oc + 0];
    if (oc + 1 < OC_) dst[1] = ay + convb[oc + 1];
    if (oc + 2 < OC_) dst[2] = az + convb[oc + 2];
    if (oc + 3 < OC_) dst[3] = aw + convb[oc + 3];
}

// ---------------- K2: hpart (float4, 1 warp/sample) ----------------
__global__ __launch_bounds__(256) void k_hpart(const int* __restrict__ inp,
        const float* __restrict__ fc1b, const float* __restrict__ emb,
        const float* __restrict__ fc1w, int nB) {
    int s = (blockIdx.x * blockDim.x + threadIdx.x) >> 5;
    int lane = threadIdx.x & 31;
    if (s >= nB) return;
    int wid = (lane < NW) ? inp[s * 105 + lane * 21] : 0;
    int ws[5];
    #pragma unroll
    for (int w = 0; w < NW; w++) ws[w] = __shfl_sync(0xffffffffu, wid, w);
    if (lane >= 25) return;   // 25 lanes * 4 = 100 j's

    const float4* WP4 = reinterpret_cast<const float4*>(g_WP);
    float4 acc = reinterpret_cast<const float4*>(fc1b)[lane];
    #pragma unroll
    for (int w = 0; w < NW; w++) {
        int c = ws[w];
        if (c < WCAP) {
            float4 v = WP4[(w * WCAP + c) * 32 + lane];
            acc.x += v.x; acc.y += v.y; acc.z += v.z; acc.w += v.w;
        } else {
            int j0 = lane * 4;
            for (int d = 0; d < WE_; d++) {
                float e = emb[c * WE_ + d];
                acc.x += e * fc1w[(j0 + 0) * 400 + w * 80 + d];
                acc.y += e * fc1w[(j0 + 1) * 400 + w * 80 + d];
                acc.z += e * fc1w[(j0 + 2) * 400 + w * 80 + d];
                acc.w += e * fc1w[(j0 + 3) * 400 + w * 80 + d];
            }
        }
    }
    reinterpret_cast<float4*>(g_hpart)[s * 32 + lane] = acc;
}

// ---------------- K3: fused fc1 + tanh + out ----------------
// 800 thr: lane(0..31) -> rows lane*4..+3 ; wy(0..24) -> cols wy*4..+3
// mainloop: FFMA2 packed fp32, W loaded as native f32x2 pairs.
// epilogue: hpart add + tanh in smem, then 36x100 out GEMM (FFMA2), coalesced store.
__global__ __launch_bounds__(NT, 2) void k_fc1(const float* __restrict__ outw,
        const float* __restrict__ outb, float* __restrict__ out, int nB) {
    extern __shared__ float sm[];
    float* Asm = sm;                          // [2][KC][AS] = 4224 floats
    float* Wsm = sm + 2 * KC * AS;            // [2][KC][100] = 3200 floats
    // epilogue overlay:
    float* Hp  = sm;                          // [128][101] = 12928
    float* Wt  = sm + 12928;                  // transposed out_w [100][36] = 3600
    float* Tmp = sm + 16528;                  // raw out_w staging / Os output [128][36]

    int tid = threadIdx.x;
    int lane = tid & 31;
    int wy = tid >> 5;
    int m0 = blockIdx.x * TM;

    int rowL = tid >> 2, kpL = tid & 3;
    bool hasA = (tid < 512);
    bool hasW = (tid < 400);
    const float4* Wp4 = reinterpret_cast<const float4*>(g_Wp);
    float4* Wc4 = reinterpret_cast<float4*>(Wsm);

    float4 pA = make_float4(0.f, 0.f, 0.f, 0.f);
    float4 pW = make_float4(0.f, 0.f, 0.f, 0.f);

    if (hasA) {
        int m = m0 + rowL;
        if (m < nB) pA = *reinterpret_cast<const float4*>(g_pool + m * KPOOL + kpL * 4);
    }
    if (hasW) pW = Wp4[tid];
    if (hasA) {
        int b0 = (kpL * 4) * AS + rowL;
        Asm[b0] = pA.x; Asm[b0 + AS] = pA.y; Asm[b0 + 2 * AS] = pA.z; Asm[b0 + 3 * AS] = pA.w;
    }
    if (hasW) Wc4[tid] = pW;
    __syncthreads();

    unsigned long long acc2[4][2];
    #pragma unroll
    for (int i = 0; i < 4; i++) { acc2[i][0] = 0ull; acc2[i][1] = 0ull; }

    for (int ck = 0; ck < NCH; ck++) {
        int b = ck & 1;
        if (ck + 1 < NCH) {
            int k0 = (ck + 1) * KC;
            if (hasA) {
                int m = m0 + rowL;
                pA = (m < nB) ? *reinterpret_cast<const float4*>(g_pool + m * KPOOL + k0 + kpL * 4)
                              : make_float4(0.f, 0.f, 0.f, 0.f);
            }
            if (hasW) pW = Wp4[(ck + 1) * 400 + tid];
        }
        const float* Ab = Asm + b * KC * AS + (lane << 2);
        const float* Wb = Wsm + b * KC * HID_ + wy * 4;
        #pragma unroll
        for (int kk = 0; kk < KC; kk++) {
            float4 a = *reinterpret_cast<const float4*>(Ab + kk * AS);
            ulonglong2 wv = *reinterpret_cast<const ulonglong2*>(Wb + kk * HID_);
            unsigned long long d0, d1, d2, d3;
            PK2(d0, a.x, a.x); PK2(d1, a.y, a.y); PK2(d2, a.z, a.z); PK2(d3, a.w, a.w);
            FMA2(acc2[0][0], d0, wv.x); FMA2(acc2[0][1], d0, wv.y);
            FMA2(acc2[1][0], d1, wv.x); FMA2(acc2[1][1], d1, wv.y);
            FMA2(acc2[2][0], d2, wv.x); FMA2(acc2[2][1], d2, wv.y);
            FMA2(acc2[3][0], d3, wv.x); FMA2(acc2[3][1], d3, wv.y);
        }
        if (ck + 1 < NCH) {
            int nb = b ^ 1;
            if (hasA) {
                int b0 = nb * KC * AS + (kpL * 4) * AS + rowL;
                Asm[b0] = pA.x; Asm[b0 + AS] = pA.y; Asm[b0 + 2 * AS] = pA.z; Asm[b0 + 3 * AS] = pA.w;
            }
            if (hasW) Wc4[nb * 400 + tid] = pW;
        }
        __syncthreads();
    }

    // ---- Phase A: stage hpart -> Hp; stage raw out_w -> Tmp ----
    for (int idx = tid; idx < 128 * 25; idx += NT) {
        int r = idx / 25, c4 = idx - r * 25;
        int m = m0 + r;
        float4 v = (m < nB) ? *reinterpret_cast<const float4*>(g_hpart + m * 128 + c4 * 4)
                            : make_float4(0.f, 0.f, 0.f, 0.f);
        int b0 = r * 101 + c4 * 4;
        Hp[b0] = v.x; Hp[b0 + 1] = v.y; Hp[b0 + 2] = v.z; Hp[b0 + 3] = v.w;
    }
    for (int idx = tid; idx < 900; idx += NT)
        reinterpret_cast<float4*>(Tmp)[idx] = reinterpret_cast<const float4*>(outw)[idx];
    __syncthreads();

    // ---- Phase B: transpose out_w; add acc + tanh ----
    for (int idx = tid; idx < TAGS_ * HID_; idx += NT) {
        int t = idx / HID_, k = idx - t * HID_;
        Wt[k * TAGS_ + t] = Tmp[idx];
    }
    #pragma unroll
    for (int i = 0; i < 4; i++) {
        int r = lane * 4 + i;
        F2U p0, p1; p0.u = acc2[i][0]; p1.u = acc2[i][1];
        int b0 = r * 101 + wy * 4;
        Hp[b0 + 0] = tanhf(p0.f.x + Hp[b0 + 0]);
        Hp[b0 + 1] = tanhf(p0.f.y + Hp[b0 + 1]);
        Hp[b0 + 2] = tanhf(p1.f.x + Hp[b0 + 2]);
        Hp[b0 + 3] = tanhf(p1.f.y + Hp[b0 + 3]);
    }
    __syncthreads();

    // ---- Phase C: out GEMM 128x36x100 (FFMA2) ----
    if (tid < 768) {
        int r = tid & 127, tg = tid >> 7;     // 6 tag-groups of 6
        unsigned long long o0 = 0ull, o1 = 0ull, o2 = 0ull;
        const float* hp = Hp + r * 101;
        const float* wt = Wt + tg * 6;
        #pragma unroll 4
        for (int k = 0; k < HID_; k++) {
            float h = hp[k];
            unsigned long long hd; PK2(hd, h, h);
            const unsigned long long* wk = reinterpret_cast<const unsigned long long*>(wt + k * TAGS_);
            FMA2(o0, hd, wk[0]);
            FMA2(o1, hd, wk[1]);
            FMA2(o2, hd, wk[2]);
        }
        F2U q0, q1, q2; q0.u = o0; q1.u = o1; q2.u = o2;
        float* os = Tmp + r * TAGS_ + tg * 6;
        os[0] = q0.f.x + outb[tg * 6 + 0];
        os[1] = q0.f.y + outb[tg * 6 + 1];
        os[2] = q1.f.x + outb[tg * 6 + 2];
        os[3] = q1.f.y + outb[tg * 6 + 3];
        os[4] = q2.f.x + outb[tg * 6 + 4];
        os[5] = q2.f.y + outb[tg * 6 + 5];
    }
    __syncthreads();

    // ---- Phase D: coalesced float4 store ----
    for (int idx = tid; idx < 128 * 9; idx += NT) {
        int r = idx / 9, c = idx - r * 9;
        int m = m0 + r;
        if (m < nB)
            *reinterpret_cast<float4*>(out + m * TAGS_ + c * 4) =
                *reinterpret_cast<const float4*>(Tmp + r * TAGS_ + c * 4);
    }
}

// ---------------- launch ----------------
extern "C" void kernel_launch(void* const* d_in, const int* in_sizes, int n_in,
                              void* d_out, int out_size) {
    const int*   inp   = (const int*)  d_in[0];
    const float* emb   = (const float*)d_in[1];
    const float* cemb  = (const float*)d_in[2];
    const float* convw = (const float*)d_in[3];
    const float* convb = (const float*)d_in[4];
    const float* fc1w  = (const float*)d_in[5];
    const float* fc1b  = (const float*)d_in[6];
    const float* outw  = (const float*)d_in[7];
    const float* outb  = (const float*)d_in[8];
    float* out = (float*)d_out;

    int nB = in_sizes[0] / (NW * (1 + NL));
    if (nB > NB_MAX) nB = NB_MAX;

    int fc1_smem = (16528 + 128 * TAGS_) * (int)sizeof(float);   // 84544 B
    cudaFuncSetAttribute(k_fc1, cudaFuncAttributeMaxDynamicSharedMemorySize, fc1_smem);

    k_init<<<128, 256>>>(emb, cemb, convw, fc1w);
    int nTasks = nB * NW;
    k_pool<<<(nTasks + 31) / 32, 256>>>(inp, convb, nTasks);
    k_hpart<<<(nB * 32 + 255) / 256, 256>>>(inp, fc1b, emb, fc1w, nB);
    k_fc1<<<(nB + TM - 1) / TM, NT, fc1_smem>>>(outw, outb, out, nB);
}

// round 8
// speedup vs baseline: 1.4191x; 1.0993x over previous
#include <cuda_runtime.h>
#include <math.h>
#include <stdint.h>

#define NB_MAX 32768
#define NW 5
#define NL 20
#define WE_ 50
#define OC_ 30
#define CE_ 32
#define HID_ 100
#define TAGS_ 36
#define KPOOL 160
#define WCAP 100
#define NPOS 18

#define TM 128
#define KC 16
#define AS 132
#define NCH (KPOOL / KC)   // 10
#define NT 640

// smem float offsets for k_fc1
#define A_OFF 0                 // [2][KC][AS] = 4224 floats
#define WU_OFF 4224             // u64 region: [2][KC][20][6] = 3840 u64 = 7680 float-slots
#define HP_OFF 11904            // [128][101] = 12928 floats
#define WID_OFF 24832           // 640 ints
#define FC1_SMEM_FLOATS 25472   // 101888 bytes
// epilogue overlays (dead Asm/Wsm region):
#define WT_OFF 0                // [100][36] = 3600 floats
#define TMP_OFF 3600            // [128][36] = 4608 floats

#define FMA2(acc, a, b) asm("fma.rn.f32x2 %0, %1, %2, %0;" : "+l"(acc) : "l"(a), "l"(b))
#define PK2(d, lo, hi) asm("mov.b64 %0, {%1, %2};" : "=l"(d) : "r"(__float_as_uint(lo)), "r"(__float_as_uint(hi)))
union F2U { unsigned long long u; float2 f; };

// ---------------- device scratch ----------------
__device__ __align__(16) float g_T[3 * 100 * 32];
__device__ __align__(16) float g_WP[NW * WCAP * 128];
__device__ __align__(16) float g_Wp[KPOOL * HID_];
__device__ __align__(16) float g_pool[NB_MAX * KPOOL];

// ---------------- K0: build T, WP, Wp ----------------
__global__ void k_init(const float* __restrict__ emb, const float* __restrict__ cemb,
                       const float* __restrict__ convw, const float* __restrict__ fc1w) {
    int stride = gridDim.x * blockDim.x;
    int t0 = blockIdx.x * blockDim.x + threadIdx.x;
    for (int idx = t0; idx < 3 * 100 * 32; idx += stride) {
        int oc = idx & 31; int rest = idx >> 5; int c = rest % 100; int k = rest / 100;
        float s = 0.f;
        if (oc < OC_) {
            #pragma unroll 8
            for (int ce = 0; ce < CE_; ce++)
                s += convw[(oc * CE_ + ce) * 3 + k] * cemb[c * CE_ + ce];
        }
        g_T[idx] = s;
    }
    for (int idx = t0; idx < NW * WCAP * HID_; idx += stride) {
        int j = idx % HID_; int rest = idx / HID_; int c = rest % WCAP; int w = rest / WCAP;
        float s = 0.f;
        #pragma unroll 10
        for (int d = 0; d < WE_; d++)
            s += emb[c * WE_ + d] * fc1w[j * 400 + w * 80 + d];
        g_WP[((w * WCAP + c) << 7) + j] = s;
    }
    for (int idx = t0; idx < KPOOL * HID_; idx += stride) {
        int j = idx % HID_; int kk = idx / HID_;
        float v = 0.f;
        if (kk < NW * OC_) {
            int w = kk / OC_, oc = kk % OC_;
            v = fc1w[j * 400 + w * 80 + WE_ + oc];
        }
        g_Wp[kk * HID_ + j] = v;
    }
}

// ---------------- K1: conv-as-table + maxpool ----------------
__global__ __launch_bounds__(256) void k_pool(const int* __restrict__ inp,
                                              const float* __restrict__ convb, int nTasks) {
    __shared__ int sch[32 * 21];
    int tid = threadIdx.x;
    int base = blockIdx.x * 32;
    int lim = nTasks * 21 - base * 21;
    for (int idx = tid; idx < 32 * 21; idx += 256)
        sch[idx] = (idx < lim) ? inp[base * 21 + idx] : 0;
    __syncthreads();

    int taskL = tid >> 3;
    int oc4 = tid & 7;
    int task = base + taskL;
    if (task >= nTasks) return;

    const float4* T4 = reinterpret_cast<const float4*>(g_T);
    const int* ch = sch + taskL * 21 + 1;
    float ax = -INFINITY, ay = -INFINITY, az = -INFINITY, aw = -INFINITY;
    #pragma unroll
    for (int p = 0; p < NPOS; p++) {
        int c0 = ch[p], c1 = ch[p + 1], c2 = ch[p + 2];
        float4 t0 = T4[(0 * 100 + c0) * 8 + oc4];
        float4 t1 = T4[(1 * 100 + c1) * 8 + oc4];
        float4 t2 = T4[(2 * 100 + c2) * 8 + oc4];
        ax = fmaxf(ax, t0.x + t1.x + t2.x);
        ay = fmaxf(ay, t0.y + t1.y + t2.y);
        az = fmaxf(az, t0.z + t1.z + t2.z);
        aw = fmaxf(aw, t0.w + t1.w + t2.w);
    }
    int s = task / NW, w = task % NW;
    int oc = oc4 * 4;
    float* dst = g_pool + s * KPOOL + w * OC_ + oc;
    if (oc + 0 < OC_) dst[0] = ax + convb[oc + 0];
    if (oc + 1 < OC_) dst[1] = ay + convb[oc + 1];
    if (oc + 2 < OC_) dst[2] = az + convb[oc + 2];
    if (oc + 3 < OC_) dst[3] = aw + convb[oc + 3];
}

// ---------------- K3: fused hpart + fc1 + tanh + out ----------------
// 640 thr = 20 warps: warp = (wr 0..3 rows) x (wc 0..4 cols)
// lane = (ml 0..7 rows) x (cl 0..3 col-groups); tile 4 rows x 5 cols / thread.
// Mainloop: A native u64 row-pairs (1 bcast wf), W pre-duplicated u64 (3 bcast wf),
// 10 FFMA2 per k-step, zero packs.
__global__ __launch_bounds__(NT, 2) void k_fc1(
        const int* __restrict__ inp, const float* __restrict__ fc1b,
        const float* __restrict__ emb, const float* __restrict__ fc1w,
        const float* __restrict__ outw, const float* __restrict__ outb,
        float* __restrict__ out, int nB) {
    extern __shared__ float sm[];
    float* Asm = sm + A_OFF;
    unsigned long long* Wu = reinterpret_cast<unsigned long long*>(sm + WU_OFF);
    float* Hp = sm + HP_OFF;
    int* sWid = reinterpret_cast<int*>(sm + WID_OFF);

    int tid = threadIdx.x;
    int m0 = blockIdx.x * TM;

    // compute-thread coords
    int warp = tid >> 5, lane = tid & 31;
    int wr = warp & 3, wc = warp >> 2;       // 4 row-warps x 5 col-warps
    int ml = lane & 7, cl = lane >> 3;       // 8 row-lanes x 4 colgroup-lanes
    int r0 = wr * 32 + ml * 4;               // 4 rows
    int g  = wc * 4 + cl;                    // col group 0..19 (5 cols each)
    int cb = g * 5;

    // loader roles
    int rowL = tid >> 2, kpL = tid & 3;
    bool hasA = (tid < 512);
    bool hasW = (tid < 400);
    int wkk = 0, wo0 = 0, wo1 = 0, wo2 = 0, wo3 = 0;
    if (hasW) {
        int flat = tid * 4;
        wkk = flat / 100;
        int c0 = flat - wkk * 100;
        wo0 = wkk * 120 + (c0 / 5) * 6 + (c0 % 5);
        wo1 = wkk * 120 + ((c0 + 1) / 5) * 6 + ((c0 + 1) % 5);
        wo2 = wkk * 120 + ((c0 + 2) / 5) * 6 + ((c0 + 2) % 5);
        wo3 = wkk * 120 + ((c0 + 3) / 5) * 6 + ((c0 + 3) % 5);
    }
    const float4* Wp4 = reinterpret_cast<const float4*>(g_Wp);

    float4 pA = make_float4(0.f, 0.f, 0.f, 0.f);
    float4 pW = make_float4(0.f, 0.f, 0.f, 0.f);

    // ---- prologue: stage chunk 0 + word ids ----
    if (hasA) {
        int m = m0 + rowL;
        if (m < nB) pA = *reinterpret_cast<const float4*>(g_pool + m * KPOOL + kpL * 4);
    }
    if (hasW) pW = Wp4[tid];
    if (hasA) {
        int b0 = (kpL * 4) * AS + rowL;
        Asm[b0] = pA.x; Asm[b0 + AS] = pA.y; Asm[b0 + 2 * AS] = pA.z; Asm[b0 + 3 * AS] = pA.w;
    }
    if (hasW) {
        unsigned long long d;
        PK2(d, pW.x, pW.x); Wu[wo0] = d;
        PK2(d, pW.y, pW.y); Wu[wo1] = d;
        PK2(d, pW.z, pW.z); Wu[wo2] = d;
        PK2(d, pW.w, pW.w); Wu[wo3] = d;
    }
    {   // word ids (640 = 128 rows x 5)
        int r = tid / 5, w = tid - (tid / 5) * 5;
        int m = m0 + r;
        sWid[tid] = (m < nB) ? inp[m * 105 + w * 21] : 0;
    }
    __syncthreads();

    // ---- hpart gather: Hp[r][j] = fc1b[j] + sum_w WP[w][wid][j] ----
    const float4* WP4 = reinterpret_cast<const float4*>(g_WP);
    const float4* fcb4 = reinterpret_cast<const float4*>(fc1b);
    #pragma unroll
    for (int it = 0; it < 5; it++) {
        int idx = it * NT + tid;            // 0..3199
        int r = idx / 25, c4 = idx - (idx / 25) * 25;
        float4 acc = fcb4[c4];
        #pragma unroll
        for (int w = 0; w < NW; w++) {
            int c = sWid[r * 5 + w];
            if (c < WCAP) {
                float4 v = WP4[(w * WCAP + c) * 32 + c4];
                acc.x += v.x; acc.y += v.y; acc.z += v.z; acc.w += v.w;
            } else {
                int j0 = c4 * 4;
                for (int d = 0; d < WE_; d++) {
                    float e = emb[c * WE_ + d];
                    acc.x += e * fc1w[(j0 + 0) * 400 + w * 80 + d];
                    acc.y += e * fc1w[(j0 + 1) * 400 + w * 80 + d];
                    acc.z += e * fc1w[(j0 + 2) * 400 + w * 80 + d];
                    acc.w += e * fc1w[(j0 + 3) * 400 + w * 80 + d];
                }
            }
        }
        int b0 = r * 101 + c4 * 4;
        Hp[b0] = acc.x; Hp[b0 + 1] = acc.y; Hp[b0 + 2] = acc.z; Hp[b0 + 3] = acc.w;
    }

    // ---- mainloop ----
    unsigned long long acc2[2][5];
    #pragma unroll
    for (int i = 0; i < 2; i++)
        #pragma unroll
        for (int c = 0; c < 5; c++) acc2[i][c] = 0ull;

    for (int ck = 0; ck < NCH; ck++) {
        int b = ck & 1;
        if (ck + 1 < NCH) {
            int k0 = (ck + 1) * KC;
            if (hasA) {
                int m = m0 + rowL;
                pA = (m < nB) ? *reinterpret_cast<const float4*>(g_pool + m * KPOOL + k0 + kpL * 4)
                              : make_float4(0.f, 0.f, 0.f, 0.f);
            }
            if (hasW) pW = Wp4[(ck + 1) * 400 + tid];
        }
        const float* Ab = Asm + b * KC * AS + r0;
        const unsigned long long* Wb = Wu + b * 1920 + g * 6;
        #pragma unroll
        for (int kk = 0; kk < KC; kk++) {
            ulonglong2 A = *reinterpret_cast<const ulonglong2*>(Ab + kk * AS);
            const unsigned long long* wp = Wb + kk * 120;
            ulonglong2 w01 = *reinterpret_cast<const ulonglong2*>(wp);
            ulonglong2 w23 = *reinterpret_cast<const ulonglong2*>(wp + 2);
            unsigned long long w4 = wp[4];
            FMA2(acc2[0][0], A.x, w01.x); FMA2(acc2[1][0], A.y, w01.x);
            FMA2(acc2[0][1], A.x, w01.y); FMA2(acc2[1][1], A.y, w01.y);
            FMA2(acc2[0][2], A.x, w23.x); FMA2(acc2[1][2], A.y, w23.x);
            FMA2(acc2[0][3], A.x, w23.y); FMA2(acc2[1][3], A.y, w23.y);
            FMA2(acc2[0][4], A.x, w4);    FMA2(acc2[1][4], A.y, w4);
        }
        if (ck + 1 < NCH) {
            int nb = b ^ 1;
            if (hasA) {
                int b0 = nb * KC * AS + (kpL * 4) * AS + rowL;
                Asm[b0] = pA.x; Asm[b0 + AS] = pA.y; Asm[b0 + 2 * AS] = pA.z; Asm[b0 + 3 * AS] = pA.w;
            }
            if (hasW) {
                unsigned long long d;
                int o = nb * 1920;
                PK2(d, pW.x, pW.x); Wu[o + wo0] = d;
                PK2(d, pW.y, pW.y); Wu[o + wo1] = d;
                PK2(d, pW.z, pW.z); Wu[o + wo2] = d;
                PK2(d, pW.w, pW.w); Wu[o + wo3] = d;
            }
        }
        __syncthreads();
    }

    // ---- Phase B: h = tanh(acc + Hp), in place; stage Wt (transposed out_w) ----
    float* Wt = sm + WT_OFF;
    for (int idx = tid; idx < TAGS_ * HID_; idx += NT) {
        int k = idx / TAGS_, t = idx - k * TAGS_;
        Wt[idx] = outw[t * HID_ + k];
    }
    #pragma unroll
    for (int rp = 0; rp < 2; rp++) {
        int r = r0 + rp * 2;
        #pragma unroll
        for (int c = 0; c < 5; c++) {
            F2U u; u.u = acc2[rp][c];
            Hp[r * 101 + cb + c]       = tanhf(u.f.x + Hp[r * 101 + cb + c]);
            Hp[(r + 1) * 101 + cb + c] = tanhf(u.f.y + Hp[(r + 1) * 101 + cb + c]);
        }
    }
    __syncthreads();

    // ---- Phase C: out GEMM 128x36x100 (FFMA2, 2 rows/thread) ----
    float* Tmp = sm + TMP_OFF;
    if (tid < 384) {
        int rg = tid & 63;            // rows rg, rg+64
        int tg = tid >> 6;            // 0..5 (uniform per warp)
        unsigned long long o0[3] = {0ull, 0ull, 0ull};
        unsigned long long o1[3] = {0ull, 0ull, 0ull};
        const float* h0p = Hp + rg * 101;
        const float* h1p = Hp + (rg + 64) * 101;
        const float* wt = Wt + tg * 6;
        #pragma unroll 4
        for (int k = 0; k < HID_; k++) {
            float h0 = h0p[k], h1 = h1p[k];
            unsigned long long hd0, hd1;
            PK2(hd0, h0, h0); PK2(hd1, h1, h1);
            const unsigned long long* wk = reinterpret_cast<const unsigned long long*>(wt + k * TAGS_);
            FMA2(o0[0], hd0, wk[0]); FMA2(o0[1], hd0, wk[1]); FMA2(o0[2], hd0, wk[2]);
            FMA2(o1[0], hd1, wk[0]); FMA2(o1[1], hd1, wk[1]); FMA2(o1[2], hd1, wk[2]);
        }
        #pragma unroll
        for (int half = 0; half < 2; half++) {
            unsigned long long* o = half ? o1 : o0;
            float* os = Tmp + (rg + half * 64) * TAGS_ + tg * 6;
            F2U q0, q1, q2; q0.u = o[0]; q1.u = o[1]; q2.u = o[2];
            os[0] = q0.f.x + outb[tg * 6 + 0];
            os[1] = q0.f.y + outb[tg * 6 + 1];
            os[2] = q1.f.x + outb[tg * 6 + 2];
            os[3] = q1.f.y + outb[tg * 6 + 3];
            os[4] = q2.f.x + outb[tg * 6 + 4];
            os[5] = q2.f.y + outb[tg * 6 + 5];
        }
    }
    __syncthreads();

    // ---- Phase D: coalesced float4 store ----
    for (int idx = tid; idx < 128 * 9; idx += NT) {
        int r = idx / 9, c = idx - r * 9;
        int m = m0 + r;
        if (m < nB)
            *reinterpret_cast<float4*>(out + m * TAGS_ + c * 4) =
                *reinterpret_cast<const float4*>(Tmp + r * TAGS_ + c * 4);
    }
}

// ---------------- launch ----------------
extern "C" void kernel_launch(void* const* d_in, const int* in_sizes, int n_in,
                              void* d_out, int out_size) {
    const int*   inp   = (const int*)  d_in[0];
    const float* emb   = (const float*)d_in[1];
    const float* cemb  = (const float*)d_in[2];
    const float* convw = (const float*)d_in[3];
    const float* convb = (const float*)d_in[4];
    const float* fc1w  = (const float*)d_in[5];
    const float* fc1b  = (const float*)d_in[6];
    const float* outw  = (const float*)d_in[7];
    const float* outb  = (const float*)d_in[8];
    float* out = (float*)d_out;

    int nB = in_sizes[0] / (NW * (1 + NL));
    if (nB > NB_MAX) nB = NB_MAX;

    int fc1_smem = FC1_SMEM_FLOATS * (int)sizeof(float);   // 101888 B
    cudaFuncSetAttribute(k_fc1, cudaFuncAttributeMaxDynamicSharedMemorySize, fc1_smem);

    k_init<<<128, 256>>>(emb, cemb, convw, fc1w);
    int nTasks = nB * NW;
    k_pool<<<(nTasks + 31) / 32, 256>>>(inp, convb, nTasks);
    k_fc1<<<(nB + TM - 1) / TM, NT, fc1_smem>>>(inp, fc1b, emb, fc1w, outw, outb, out, nB);
}

// round 13
// speedup vs baseline: 1.4810x; 1.0436x over previous
#include <cuda_runtime.h>
#include <math.h>
#include <stdint.h>

#define NB_MAX 32768
#define NW 5
#define NL 20
#define WE_ 50
#define OC_ 30
#define CE_ 32
#define HID_ 100
#define TAGS_ 36
#define KPOOL 160
#define WCAP 100
#define NPOS 18

#define TM 128
#define KC 16
#define AS 132
#define NCH (KPOOL / KC)   // 10
#define NT 640

// smem float offsets for k_fc1
#define A_OFF 0                 // [2][KC][AS] = 4224 floats
#define WU_OFF 4224             // u64 region: [2][KC][20][6] = 3840 u64 = 7680 float-slots
#define HP_OFF 11904            // [128][101] = 12928 floats
#define WID_OFF 24832           // 640 ints
#define FC1_SMEM_FLOATS 25472   // 101888 bytes
// epilogue overlays (dead Asm/Wsm region):
#define WT_OFF 0                // [100][36] = 3600 floats
#define TMP_OFF 3600            // [128][36] = 4608 floats

#define FMA2(acc, a, b) asm("fma.rn.f32x2 %0, %1, %2, %0;" : "+l"(acc) : "l"(a), "l"(b))
#define PK2(d, lo, hi) asm("mov.b64 %0, {%1, %2};" : "=l"(d) : "r"(__float_as_uint(lo)), "r"(__float_as_uint(hi)))
union F2U { unsigned long long u; float2 f; };

// ---------------- device scratch ----------------
__device__ __align__(16) float g_T[3 * 100 * 32];
__device__ __align__(16) float g_WP[NW * WCAP * 128];
__device__ __align__(16) float g_Wp[KPOOL * HID_];
__device__ __align__(16) float g_pool[NB_MAX * KPOOL];

// ---------------- K0: conv table T only (pool's only dependency) ----------------
__global__ __launch_bounds__(128) void k_initT(const float* __restrict__ cemb,
                                               const float* __restrict__ convw) {
    int idx = blockIdx.x * 128 + threadIdx.x;      // grid 75*128 = 9600 exact
    int oc = idx & 31; int rest = idx >> 5; int c = rest % 100; int k = rest / 100;
    float s = 0.f;
    if (oc < OC_) {
        #pragma unroll 8
        for (int ce = 0; ce < CE_; ce++)
            s += convw[(oc * CE_ + ce) * 3 + k] * cemb[c * CE_ + ce];
    }
    g_T[idx] = s;
}

// ---------------- K1: pool + (fused) WP/Wp builds in extra blocks ----------------
__global__ __launch_bounds__(256) void k_poolw(const int* __restrict__ inp,
        const float* __restrict__ convb, const float* __restrict__ emb,
        const float* __restrict__ fc1w, int nTasks, int nPool) {
    int blk = blockIdx.x;
    int tid = threadIdx.x;

    if (blk >= nPool) {
        // -------- init-W blocks (concurrent with pool; no dependency) --------
        int ib = blk - nPool;
        if (ib < 500) {
            // WP[w][c][j] = emb[c] . fc1_w[j, w*80 : w*80+50]
            __shared__ float semb[WE_];
            int w = ib / 100, c = ib - (ib / 100) * 100;
            if (tid < WE_) semb[tid] = emb[c * WE_ + tid];
            __syncthreads();
            if (tid < HID_) {
                const float* fw = fc1w + tid * 400 + w * 80;
                float s0 = 0.f, s1 = 0.f;
                #pragma unroll
                for (int d = 0; d < WE_; d += 2) {
                    s0 += semb[d] * fw[d];
                    s1 += semb[d + 1] * fw[d + 1];
                }
                g_WP[((w * WCAP + c) << 7) + tid] = s0 + s1;
            }
        } else {
            // Wp[k][j]: pooled part of fc1_w, zero-pad k>=150
            int idx = (ib - 500) * 256 + tid;
            if (idx < KPOOL * HID_) {
                int j = idx % HID_; int kk = idx / HID_;
                float v = 0.f;
                if (kk < NW * OC_) {
                    int w = kk / OC_, oc = kk % OC_;
                    v = fc1w[j * 400 + w * 80 + WE_ + oc];
                }
                g_Wp[idx] = v;
            }
        }
        return;
    }

    // -------- pool blocks: conv-as-table + maxpool --------
    __shared__ int sch[32 * 21];
    int base = blk * 32;
    int lim = nTasks * 21 - base * 21;
    for (int idx = tid; idx < 32 * 21; idx += 256)
        sch[idx] = (idx < lim) ? inp[base * 21 + idx] : 0;
    __syncthreads();

    int taskL = tid >> 3;
    int oc4 = tid & 7;
    int task = base + taskL;
    if (task >= nTasks) return;

    const float4* T4 = reinterpret_cast<const float4*>(g_T);
    const int* ch = sch + taskL * 21 + 1;
    float ax = -INFINITY, ay = -INFINITY, az = -INFINITY, aw = -INFINITY;
    #pragma unroll
    for (int p = 0; p < NPOS; p++) {
        int c0 = ch[p], c1 = ch[p + 1], c2 = ch[p + 2];
        float4 t0 = T4[(0 * 100 + c0) * 8 + oc4];
        float4 t1 = T4[(1 * 100 + c1) * 8 + oc4];
        float4 t2 = T4[(2 * 100 + c2) * 8 + oc4];
        ax = fmaxf(ax, t0.x + t1.x + t2.x);
        ay = fmaxf(ay, t0.y + t1.y + t2.y);
        az = fmaxf(az, t0.z + t1.z + t2.z);
        aw = fmaxf(aw, t0.w + t1.w + t2.w);
    }
    int s = task / NW, w = task % NW;
    int oc = oc4 * 4;
    float* dst = g_pool + s * KPOOL + w * OC_ + oc;
    if (oc + 0 < OC_) dst[0] = ax + convb[oc + 0];
    if (oc + 1 < OC_) dst[1] = ay + convb[oc + 1];
    if (oc + 2 < OC_) dst[2] = az + convb[oc + 2];
    if (oc + 3 < OC_) dst[3] = aw + convb[oc + 3];
}

// ---------------- K3: fused hpart + fc1 + tanh + out ----------------
// 640 thr = 20 warps: warp = (wr 0..3 rows) x (wc 0..4 cols)
// lane = (ml 0..7 rows) x (cl 0..3 col-groups); tile 4 rows x 5 cols / thread.
__global__ __launch_bounds__(NT, 2) void k_fc1(
        const int* __restrict__ inp, const float* __restrict__ fc1b,
        const float* __restrict__ emb, const float* __restrict__ fc1w,
        const float* __restrict__ outw, const float* __restrict__ outb,
        float* __restrict__ out, int nB) {
    extern __shared__ float sm[];
    float* Asm = sm + A_OFF;
    unsigned long long* Wu = reinterpret_cast<unsigned long long*>(sm + WU_OFF);
    float* Hp = sm + HP_OFF;
    int* sWid = reinterpret_cast<int*>(sm + WID_OFF);

    int tid = threadIdx.x;
    int m0 = blockIdx.x * TM;

    int warp = tid >> 5, lane = tid & 31;
    int wr = warp & 3, wc = warp >> 2;
    int ml = lane & 7, cl = lane >> 3;
    int r0 = wr * 32 + ml * 4;
    int g  = wc * 4 + cl;
    int cb = g * 5;

    int rowL = tid >> 2, kpL = tid & 3;
    bool hasA = (tid < 512);
    bool hasW = (tid < 400);
    int wkk = 0, wo0 = 0, wo1 = 0, wo2 = 0, wo3 = 0;
    if (hasW) {
        int flat = tid * 4;
        wkk = flat / 100;
        int c0 = flat - wkk * 100;
        wo0 = wkk * 120 + (c0 / 5) * 6 + (c0 % 5);
        wo1 = wkk * 120 + ((c0 + 1) / 5) * 6 + ((c0 + 1) % 5);
        wo2 = wkk * 120 + ((c0 + 2) / 5) * 6 + ((c0 + 2) % 5);
        wo3 = wkk * 120 + ((c0 + 3) / 5) * 6 + ((c0 + 3) % 5);
    }
    const float4* Wp4 = reinterpret_cast<const float4*>(g_Wp);

    float4 pA = make_float4(0.f, 0.f, 0.f, 0.f);
    float4 pW = make_float4(0.f, 0.f, 0.f, 0.f);

    if (hasA) {
        int m = m0 + rowL;
        if (m < nB) pA = *reinterpret_cast<const float4*>(g_pool + m * KPOOL + kpL * 4);
    }
    if (hasW) pW = Wp4[tid];
    if (hasA) {
        int b0 = (kpL * 4) * AS + rowL;
        Asm[b0] = pA.x; Asm[b0 + AS] = pA.y; Asm[b0 + 2 * AS] = pA.z; Asm[b0 + 3 * AS] = pA.w;
    }
    if (hasW) {
        unsigned long long d;
        PK2(d, pW.x, pW.x); Wu[wo0] = d;
        PK2(d, pW.y, pW.y); Wu[wo1] = d;
        PK2(d, pW.z, pW.z); Wu[wo2] = d;
        PK2(d, pW.w, pW.w); Wu[wo3] = d;
    }
    {
        int r = tid / 5, w = tid - (tid / 5) * 5;
        int m = m0 + r;
        sWid[tid] = (m < nB) ? inp[m * 105 + w * 21] : 0;
    }
    __syncthreads();

    // ---- hpart gather ----
    const float4* WP4 = reinterpret_cast<const float4*>(g_WP);
    const float4* fcb4 = reinterpret_cast<const float4*>(fc1b);
    #pragma unroll
    for (int it = 0; it < 5; it++) {
        int idx = it * NT + tid;
        int r = idx / 25, c4 = idx - (idx / 25) * 25;
        float4 acc = fcb4[c4];
        #pragma unroll
        for (int w = 0; w < NW; w++) {
            int c = sWid[r * 5 + w];
            if (c < WCAP) {
                float4 v = WP4[(w * WCAP + c) * 32 + c4];
                acc.x += v.x; acc.y += v.y; acc.z += v.z; acc.w += v.w;
            } else {
                int j0 = c4 * 4;
                for (int d = 0; d < WE_; d++) {
                    float e = emb[c * WE_ + d];
                    acc.x += e * fc1w[(j0 + 0) * 400 + w * 80 + d];
                    acc.y += e * fc1w[(j0 + 1) * 400 + w * 80 + d];
                    acc.z += e * fc1w[(j0 + 2) * 400 + w * 80 + d];
                    acc.w += e * fc1w[(j0 + 3) * 400 + w * 80 + d];
                }
            }
        }
        int b0 = r * 101 + c4 * 4;
        Hp[b0] = acc.x; Hp[b0 + 1] = acc.y; Hp[b0 + 2] = acc.z; Hp[b0 + 3] = acc.w;
    }

    // ---- mainloop ----
    unsigned long long acc2[2][5];
    #pragma unroll
    for (int i = 0; i < 2; i++)
        #pragma unroll
        for (int c = 0; c < 5; c++) acc2[i][c] = 0ull;

    for (int ck = 0; ck < NCH; ck++) {
        int b = ck & 1;
        if (ck + 1 < NCH) {
            int k0 = (ck + 1) * KC;
            if (hasA) {
                int m = m0 + rowL;
                pA = (m < nB) ? *reinterpret_cast<const float4*>(g_pool + m * KPOOL + k0 + kpL * 4)
                              : make_float4(0.f, 0.f, 0.f, 0.f);
            }
            if (hasW) pW = Wp4[(ck + 1) * 400 + tid];
        }
        const float* Ab = Asm + b * KC * AS + r0;
        const unsigned long long* Wb = Wu + b * 1920 + g * 6;
        #pragma unroll
        for (int kk = 0; kk < KC; kk++) {
            ulonglong2 A = *reinterpret_cast<const ulonglong2*>(Ab + kk * AS);
            const unsigned long long* wp = Wb + kk * 120;
            ulonglong2 w01 = *reinterpret_cast<const ulonglong2*>(wp);
            ulonglong2 w23 = *reinterpret_cast<const ulonglong2*>(wp + 2);
            unsigned long long w4 = wp[4];
            FMA2(acc2[0][0], A.x, w01.x); FMA2(acc2[1][0], A.y, w01.x);
            FMA2(acc2[0][1], A.x, w01.y); FMA2(acc2[1][1], A.y, w01.y);
            FMA2(acc2[0][2], A.x, w23.x); FMA2(acc2[1][2], A.y, w23.x);
            FMA2(acc2[0][3], A.x, w23.y); FMA2(acc2[1][3], A.y, w23.y);
            FMA2(acc2[0][4], A.x, w4);    FMA2(acc2[1][4], A.y, w4);
        }
        if (ck + 1 < NCH) {
            int nb = b ^ 1;
            if (hasA) {
                int b0 = nb * KC * AS + (kpL * 4) * AS + rowL;
                Asm[b0] = pA.x; Asm[b0 + AS] = pA.y; Asm[b0 + 2 * AS] = pA.z; Asm[b0 + 3 * AS] = pA.w;
            }
            if (hasW) {
                unsigned long long d;
                int o = nb * 1920;
                PK2(d, pW.x, pW.x); Wu[o + wo0] = d;
                PK2(d, pW.y, pW.y); Wu[o + wo1] = d;
                PK2(d, pW.z, pW.z); Wu[o + wo2] = d;
                PK2(d, pW.w, pW.w); Wu[o + wo3] = d;
            }
        }
        __syncthreads();
    }

    // ---- Phase B: h = tanh(acc + Hp); stage Wt ----
    float* Wt = sm + WT_OFF;
    for (int idx = tid; idx < TAGS_ * HID_; idx += NT) {
        int k = idx / TAGS_, t = idx - k * TAGS_;
        Wt[idx] = outw[t * HID_ + k];
    }
    #pragma unroll
    for (int rp = 0; rp < 2; rp++) {
        int r = r0 + rp * 2;
        #pragma unroll
        for (int c = 0; c < 5; c++) {
            F2U u; u.u = acc2[rp][c];
            Hp[r * 101 + cb + c]       = tanhf(u.f.x + Hp[r * 101 + cb + c]);
            Hp[(r + 1) * 101 + cb + c] = tanhf(u.f.y + Hp[(r + 1) * 101 + cb + c]);
        }
    }
    __syncthreads();

    // ---- Phase C: out GEMM 128x36x100 ----
    float* Tmp = sm + TMP_OFF;
    if (tid < 384) {
        int rg = tid & 63;
        int tg = tid >> 6;
        unsigned long long o0[3] = {0ull, 0ull, 0ull};
        unsigned long long o1[3] = {0ull, 0ull, 0ull};
        const float* h0p = Hp + rg * 101;
        const float* h1p = Hp + (rg + 64) * 101;
        const float* wt = Wt + tg * 6;
        #pragma unroll 4
        for (int k = 0; k < HID_; k++) {
            float h0 = h0p[k], h1 = h1p[k];
            unsigned long long hd0, hd1;
            PK2(hd0, h0, h0); PK2(hd1, h1, h1);
            const unsigned long long* wk = reinterpret_cast<const unsigned long long*>(wt + k * TAGS_);
            FMA2(o0[0], hd0, wk[0]); FMA2(o0[1], hd0, wk[1]); FMA2(o0[2], hd0, wk[2]);
            FMA2(o1[0], hd1, wk[0]); FMA2(o1[1], hd1, wk[1]); FMA2(o1[2], hd1, wk[2]);
        }
        #pragma unroll
        for (int half = 0; half < 2; half++) {
            unsigned long long* o = half ? o1 : o0;
            float* os = Tmp + (rg + half * 64) * TAGS_ + tg * 6;
            F2U q0, q1, q2; q0.u = o[0]; q1.u = o[1]; q2.u = o[2];
            os[0] = q0.f.x + outb[tg * 6 + 0];
            os[1] = q0.f.y + outb[tg * 6 + 1];
            os[2] = q1.f.x + outb[tg * 6 + 2];
            os[3] = q1.f.y + outb[tg * 6 + 3];
            os[4] = q2.f.x + outb[tg * 6 + 4];
            os[5] = q2.f.y + outb[tg * 6 + 5];
        }
    }
    __syncthreads();

    // ---- Phase D: coalesced float4 store ----
    for (int idx = tid; idx < 128 * 9; idx += NT) {
        int r = idx / 9, c = idx - r * 9;
        int m = m0 + r;
        if (m < nB)
            *reinterpret_cast<float4*>(out + m * TAGS_ + c * 4) =
                *reinterpret_cast<const float4*>(Tmp + r * TAGS_ + c * 4);
    }
}

// ---------------- launch ----------------
extern "C" void kernel_launch(void* const* d_in, const int* in_sizes, int n_in,
                              void* d_out, int out_size) {
    const int*   inp   = (const int*)  d_in[0];
    const float* emb   = (const float*)d_in[1];
    const float* cemb  = (const float*)d_in[2];
    const float* convw = (const float*)d_in[3];
    const float* convb = (const float*)d_in[4];
    const float* fc1w  = (const float*)d_in[5];
    const float* fc1b  = (const float*)d_in[6];
    const float* outw  = (const float*)d_in[7];
    const float* outb  = (const float*)d_in[8];
    float* out = (float*)d_out;

    int nB = in_sizes[0] / (NW * (1 + NL));
    if (nB > NB_MAX) nB = NB_MAX;

    int fc1_smem = FC1_SMEM_FLOATS * (int)sizeof(float);   // 101888 B
    cudaFuncSetAttribute(k_fc1, cudaFuncAttributeMaxDynamicSharedMemorySize, fc1_smem);

    k_initT<<<75, 128>>>(cemb, convw);
    int nTasks = nB * NW;
    int nPool = (nTasks + 31) / 32;
    k_poolw<<<nPool + 563, 256>>>(inp, convb, emb, fc1w, nTasks, nPool);
    k_fc1<<<(nB + TM - 1) / TM, NT, fc1_smem>>>(inp, fc1b, emb, fc1w, outw, outb, out, nB);
}